// round 8
// baseline (speedup 1.0000x reference)
#include <cuda_runtime.h>
#include <cuda_bf16.h>

#define TS2 36   // smem row stride in float2 units (34 used + 2 pad; 288B/row)

using ull = unsigned long long;

// ---- packed f32x2 helpers (sm_100+ PTX; ptxas never auto-fuses these) ----
__device__ __forceinline__ ull pack2(float lo, float hi) {
    ull r;
    asm("mov.b64 %0, {%1, %2};" : "=l"(r)
        : "r"(__float_as_uint(lo)), "r"(__float_as_uint(hi)));
    return r;
}
__device__ __forceinline__ void unpack2(ull v, float& lo, float& hi) {
    unsigned a, b;
    asm("mov.b64 {%0, %1}, %2;" : "=r"(a), "=r"(b) : "l"(v));
    lo = __uint_as_float(a); hi = __uint_as_float(b);
}
__device__ __forceinline__ ull ffma2(ull a, ull b, ull c) {
    ull d; asm("fma.rn.f32x2 %0, %1, %2, %3;" : "=l"(d) : "l"(a), "l"(b), "l"(c));
    return d;
}
__device__ __forceinline__ ull fmul2(ull a, ull b) {
    ull d; asm("mul.rn.f32x2 %0, %1, %2;" : "=l"(d) : "l"(a), "l"(b));
    return d;
}
__device__ __forceinline__ ull fadd2(ull a, ull b) {
    ull d; asm("add.rn.f32x2 %0, %1, %2;" : "=l"(d) : "l"(a), "l"(b));
    return d;
}

__global__ __launch_bounds__(256, 6)
void quan2d_kernel(const float4* __restrict__ x4,
                   const float* __restrict__ w,
                   float4* __restrict__ out4)
{
    // Interleaved 34x34 zero-padded tile: tile[r*TS2 + c] = { img0[r][c], img1[r][c] }.
    // One LDS.64 yields a packed f32x2 amplitude directly — no register shuffles.
    __shared__ float2 tile[34 * TS2];
    __shared__ ull grp[8], grn[8];   // packed {r,r} and {-r,-r}, r = tan(theta/2)

    const int tid  = threadIdx.x;
    const int img0 = blockIdx.x * 2;

    if (tid < 8) {
        float sv, cv;
        sincosf(w[tid] * 0.5f, &sv, &cv);
        float r = __fdividef(sv, cv);   // cosine factor cancels in <Z> = 1 - 2s/nrm
        grp[tid] = pack2(r, r);
        grn[tid] = pack2(-r, -r);
    }

    // Zero the padding (float4 = 2 interleaved pixels):
    // right border cols 32..35, rows 0..33: 2 float4/row x 34 rows = 68
    // bottom rows 32..33, cols 0..31: 16 float4/row x 2 rows = 32
    {
        const float4 z4 = make_float4(0.f, 0.f, 0.f, 0.f);
        if (tid < 68) {
            int r = tid >> 1, half = tid & 1;
            *reinterpret_cast<float4*>(&tile[r * TS2 + 32 + half * 2]) = z4;
        } else if (tid < 100) {
            int t = tid - 68;                  // 0..31
            int r = 32 + (t >> 4), q = t & 15; // q -> cols 2q..2q+1
            *reinterpret_cast<float4*>(&tile[r * TS2 + q * 2]) = z4;
        }
    }

    // Coalesced load of both 32x32 images, stored interleaved (2 STS.128/thread)
    {
        float4 v0 = x4[img0 * 256 + tid];
        float4 v1 = x4[(img0 + 1) * 256 + tid];
        int r = tid >> 3, c4 = (tid & 7) << 2;
        float4 lo = make_float4(v0.x, v1.x, v0.y, v1.y);
        float4 hi = make_float4(v0.z, v1.z, v0.w, v1.w);
        *reinterpret_cast<float4*>(&tile[r * TS2 + c4])     = lo;
        *reinterpret_cast<float4*>(&tile[r * TS2 + c4 + 2]) = hi;
    }
    __syncthreads();

    // Patch tid = (ph, pw); rows 2ph..2ph+3, cols 2pw..2pw+3 of the padded 34x34.
    const int ph = tid >> 4, pw = tid & 15;
    const ull* pbase = reinterpret_cast<const ull*>(&tile[(ph * 2) * TS2 + (pw * 2)]);

    // Amplitudes packed {img0, img1}: flat j = dr*4 + dc; wire0 = MSB (mask 8)
    ull a[16];
#pragma unroll
    for (int dr = 0; dr < 4; ++dr)
#pragma unroll
        for (int dc = 0; dc < 4; ++dc)
            a[dr * 4 + dc] = pbase[dr * TS2 + dc];   // LDS.64, already packed

    // RY (tangent form, cosine deferred): new0 = t0 - r*t1 ; new1 = r*t0 + t1
    auto ry = [&](int m, int gi) {
        ull r2  = grp[gi];   // LDS.64 of pre-packed constants
        ull nr2 = grn[gi];
#pragma unroll
        for (int j = 0; j < 16; ++j) {
            if (j & m) continue;
            ull t0 = a[j], t1 = a[j | m];
            a[j]     = ffma2(nr2, t1, t0);
            a[j | m] = ffma2(r2,  t0, t1);
        }
    };
    // CNOT = compile-time register permutation (free)
    auto cnot = [&](int cb, int tb) {
#pragma unroll
        for (int j = 0; j < 16; ++j)
            if ((j & cb) && !(j & tb)) { ull t = a[j]; a[j] = a[j | tb]; a[j | tb] = t; }
    };

    ry(8, 0); ry(4, 1); ry(2, 2); ry(1, 3);
    cnot(8, 4); cnot(4, 2); cnot(2, 1); cnot(1, 8);
    ry(8, 4); ry(4, 5); ry(2, 6); ry(1, 7);

    // Group sums of squares:
    //   G[g] = sum a[j]^2, j with (bit3,bit2) = g   (j = g*4 + k)
    //   H[g] = sum a[j]^2, j with (bit1,bit0) = g   (j = k*4 + g)
    ull G[4], H[4];
#pragma unroll
    for (int g = 0; g < 4; ++g) {
        ull acc = fmul2(a[g * 4], a[g * 4]);
#pragma unroll
        for (int k = 1; k < 4; ++k) acc = ffma2(a[g * 4 + k], a[g * 4 + k], acc);
        G[g] = acc;
        ull acc2 = fmul2(a[g], a[g]);
#pragma unroll
        for (int k = 1; k < 4; ++k) acc2 = ffma2(a[k * 4 + g], a[k * 4 + g], acc2);
        H[g] = acc2;
    }
    ull nrm2 = fadd2(fadd2(G[0], G[1]), fadd2(G[2], G[3]));
    ull s0p = fadd2(G[2], G[3]);   // wire0 (bit3 set)
    ull s1p = fadd2(G[1], G[3]);   // wire1 (bit2 set)
    ull s2p = fadd2(H[2], H[3]);   // wire2 (bit1 set)
    ull s3p = fadd2(H[1], H[3]);   // wire3 (bit0 set)

    // <Z_w> = 1 - 2*s_w/nrm
    float n0, n1;
    unpack2(nrm2, n0, n1);
    ull m2inv = pack2(__fdividef(-2.0f, n0), __fdividef(-2.0f, n1));
    ull ones  = pack2(1.0f, 1.0f);

    ull z0 = ffma2(s0p, m2inv, ones);
    ull z1 = ffma2(s1p, m2inv, ones);
    ull z2 = ffma2(s2p, m2inv, ones);
    ull z3 = ffma2(s3p, m2inv, ones);

    float4 o0, o1;
    unpack2(z0, o0.x, o1.x);
    unpack2(z1, o0.y, o1.y);
    unpack2(z2, o0.z, o1.z);
    unpack2(z3, o0.w, o1.w);

    out4[img0 * 256 + tid]       = o0;
    out4[(img0 + 1) * 256 + tid] = o1;
}

extern "C" void kernel_launch(void* const* d_in, const int* in_sizes, int n_in,
                              void* d_out, int out_size)
{
    const float* x = (const float*)d_in[0];
    const float* w = (const float*)d_in[1];
    if (n_in >= 2 && in_sizes[0] == 8) {   // defensive input-order resolution
        x = (const float*)d_in[1];
        w = (const float*)d_in[0];
    }
    quan2d_kernel<<<4096, 256>>>((const float4*)x, w, (float4*)d_out);
}

// round 9
// speedup vs baseline: 1.2796x; 1.2796x over previous
#include <cuda_runtime.h>
#include <cuda_bf16.h>

#define TS 36   // smem row stride in floats (34 used + 2 pad; 144B keeps float4 alignment)

using ull = unsigned long long;

// ---- packed f32x2 helpers (sm_100+ PTX; ptxas never auto-fuses these) ----
__device__ __forceinline__ ull pack2(float lo, float hi) {
    ull r;
    asm("mov.b64 %0, {%1, %2};" : "=l"(r)
        : "r"(__float_as_uint(lo)), "r"(__float_as_uint(hi)));
    return r;
}
__device__ __forceinline__ void unpack2(ull v, float& lo, float& hi) {
    unsigned a, b;
    asm("mov.b64 {%0, %1}, %2;" : "=r"(a), "=r"(b) : "l"(v));
    lo = __uint_as_float(a); hi = __uint_as_float(b);
}
__device__ __forceinline__ ull ffma2(ull a, ull b, ull c) {
    ull d; asm("fma.rn.f32x2 %0, %1, %2, %3;" : "=l"(d) : "l"(a), "l"(b), "l"(c));
    return d;
}
__device__ __forceinline__ ull fmul2(ull a, ull b) {
    ull d; asm("mul.rn.f32x2 %0, %1, %2;" : "=l"(d) : "l"(a), "l"(b));
    return d;
}
__device__ __forceinline__ ull fadd2(ull a, ull b) {
    ull d; asm("add.rn.f32x2 %0, %1, %2;" : "=l"(d) : "l"(a), "l"(b));
    return d;
}

__global__ __launch_bounds__(256, 5)
void quan2d_kernel(const float4* __restrict__ x4,
                   const float* __restrict__ w,
                   float4* __restrict__ out4)
{
    // Two separate 34x34 zero-padded image tiles (proven conflict-free layout).
    __shared__ float tile[2][34 * TS];
    __shared__ ull grp[8], grn[8];   // pre-packed {r,r} / {-r,-r}, r = tan(theta/2)

    const int tid  = threadIdx.x;
    const int img0 = blockIdx.x * 2;

    if (tid < 8) {
        float sv, cv;
        sincosf(w[tid] * 0.5f, &sv, &cv);
        float r = __fdividef(sv, cv);   // cosine factor cancels in <Z> = 1 - 2s/nrm
        grp[tid] = pack2(r, r);
        grn[tid] = pack2(-r, -r);
    }

    // Zero the padding: cols 32..35 rows 0..33 (34 f4/img), rows 32..33 cols 0..31 (16 f4/img)
    {
        const float4 z4 = make_float4(0.f, 0.f, 0.f, 0.f);
        if (tid < 68) {                       // right border
            int im = tid & 1, r = tid >> 1;
            *reinterpret_cast<float4*>(&tile[im][r * TS + 32]) = z4;
        } else if (tid < 100) {               // bottom rows
            int t = tid - 68;
            int im = t >> 4;
            int q  = t & 15;
            *reinterpret_cast<float4*>(&tile[im][(32 + (q >> 3)) * TS + ((q & 7) << 2)]) = z4;
        }
    }

    // Coalesced load of both 32x32 images (256 threads x 2 float4, STS.128)
    {
        float4 v0 = x4[img0 * 256 + tid];
        float4 v1 = x4[(img0 + 1) * 256 + tid];
        int r = tid >> 3, c4 = (tid & 7) << 2;
        *reinterpret_cast<float4*>(&tile[0][r * TS + c4]) = v0;
        *reinterpret_cast<float4*>(&tile[1][r * TS + c4]) = v1;
    }
    __syncthreads();

    // Patch tid = (ph, pw); rows 2ph..2ph+3, cols 2pw..2pw+3 of the padded 34x34.
    const int ph = tid >> 4, pw = tid & 15;
    const int base = (ph * 2) * TS + (pw * 2);

    // Amplitudes packed {img0, img1} via scalar LDS.32 pairs — ptxas allocates the
    // two load destinations into the aligned pair, so pack2 MOVs elide.
    ull a[16];
#pragma unroll
    for (int dr = 0; dr < 4; ++dr)
#pragma unroll
        for (int dc = 0; dc < 4; ++dc) {
            int idx = base + dr * TS + dc;
            a[dr * 4 + dc] = pack2(tile[0][idx], tile[1][idx]);
        }

    // RY (tangent form, cosine deferred): new0 = t0 - r*t1 ; new1 = r*t0 + t1
    auto ry = [&](int m, int gi) {
        ull r2  = grp[gi];   // LDS.64 broadcast of pre-packed constants
        ull nr2 = grn[gi];
#pragma unroll
        for (int j = 0; j < 16; ++j) {
            if (j & m) continue;
            ull t0 = a[j], t1 = a[j | m];
            a[j]     = ffma2(nr2, t1, t0);
            a[j | m] = ffma2(r2,  t0, t1);
        }
    };
    // CNOT = compile-time register permutation (free)
    auto cnot = [&](int cb, int tb) {
#pragma unroll
        for (int j = 0; j < 16; ++j)
            if ((j & cb) && !(j & tb)) { ull t = a[j]; a[j] = a[j | tb]; a[j | tb] = t; }
    };

    ry(8, 0); ry(4, 1); ry(2, 2); ry(1, 3);
    cnot(8, 4); cnot(4, 2); cnot(2, 1); cnot(1, 8);
    ry(8, 4); ry(4, 5); ry(2, 6); ry(1, 7);

    // Group sums of squares:
    //   G[g] = sum a[j]^2, j with (bit3,bit2) = g   (j = g*4 + k)
    //   H[g] = sum a[j]^2, j with (bit1,bit0) = g   (j = k*4 + g)
    ull G[4], H[4];
#pragma unroll
    for (int g = 0; g < 4; ++g) {
        ull acc = fmul2(a[g * 4], a[g * 4]);
#pragma unroll
        for (int k = 1; k < 4; ++k) acc = ffma2(a[g * 4 + k], a[g * 4 + k], acc);
        G[g] = acc;
        ull acc2 = fmul2(a[g], a[g]);
#pragma unroll
        for (int k = 1; k < 4; ++k) acc2 = ffma2(a[k * 4 + g], a[k * 4 + g], acc2);
        H[g] = acc2;
    }
    ull nrm2 = fadd2(fadd2(G[0], G[1]), fadd2(G[2], G[3]));
    ull s0p = fadd2(G[2], G[3]);   // wire0 (bit3 set)
    ull s1p = fadd2(G[1], G[3]);   // wire1 (bit2 set)
    ull s2p = fadd2(H[2], H[3]);   // wire2 (bit1 set)
    ull s3p = fadd2(H[1], H[3]);   // wire3 (bit0 set)

    // <Z_w> = 1 - 2*s_w/nrm
    float n0, n1;
    unpack2(nrm2, n0, n1);
    ull m2inv = pack2(__fdividef(-2.0f, n0), __fdividef(-2.0f, n1));
    ull ones  = pack2(1.0f, 1.0f);

    ull z0 = ffma2(s0p, m2inv, ones);
    ull z1 = ffma2(s1p, m2inv, ones);
    ull z2 = ffma2(s2p, m2inv, ones);
    ull z3 = ffma2(s3p, m2inv, ones);

    float4 o0, o1;
    unpack2(z0, o0.x, o1.x);
    unpack2(z1, o0.y, o1.y);
    unpack2(z2, o0.z, o1.z);
    unpack2(z3, o0.w, o1.w);

    out4[img0 * 256 + tid]       = o0;
    out4[(img0 + 1) * 256 + tid] = o1;
}

extern "C" void kernel_launch(void* const* d_in, const int* in_sizes, int n_in,
                              void* d_out, int out_size)
{
    const float* x = (const float*)d_in[0];
    const float* w = (const float*)d_in[1];
    if (n_in >= 2 && in_sizes[0] == 8) {   // defensive input-order resolution
        x = (const float*)d_in[1];
        w = (const float*)d_in[0];
    }
    quan2d_kernel<<<4096, 256>>>((const float4*)x, w, (float4*)d_out);
}

// round 10
// speedup vs baseline: 1.3031x; 1.0184x over previous
#include <cuda_runtime.h>
#include <cuda_bf16.h>

#define TS2 36   // smem row stride in float2 units (34 used + 2 pad; even -> float4 aligned)

using ull = unsigned long long;

// ---- packed f32x2 helpers (sm_100+ PTX; ptxas never auto-fuses these) ----
__device__ __forceinline__ ull pack2(float lo, float hi) {
    ull r;
    asm("mov.b64 %0, {%1, %2};" : "=l"(r)
        : "r"(__float_as_uint(lo)), "r"(__float_as_uint(hi)));
    return r;
}
__device__ __forceinline__ void unpack2(ull v, float& lo, float& hi) {
    unsigned a, b;
    asm("mov.b64 {%0, %1}, %2;" : "=r"(a), "=r"(b) : "l"(v));
    lo = __uint_as_float(a); hi = __uint_as_float(b);
}
__device__ __forceinline__ ull ffma2(ull a, ull b, ull c) {
    ull d; asm("fma.rn.f32x2 %0, %1, %2, %3;" : "=l"(d) : "l"(a), "l"(b), "l"(c));
    return d;
}
__device__ __forceinline__ ull fmul2(ull a, ull b) {
    ull d; asm("mul.rn.f32x2 %0, %1, %2;" : "=l"(d) : "l"(a), "l"(b));
    return d;
}
__device__ __forceinline__ ull fadd2(ull a, ull b) {
    ull d; asm("add.rn.f32x2 %0, %1, %2;" : "=l"(d) : "l"(a), "l"(b));
    return d;
}

__global__ __launch_bounds__(256, 5)
void quan2d_kernel(const float4* __restrict__ x4,
                   const float* __restrict__ w,
                   float4* __restrict__ out4)
{
    // Interleaved zero-padded 34x34 tile: tile[r*TS2 + c] = { img0[r][c], img1[r][c] }.
    // A patch row (4 cols, even start) = 2 aligned float4 = 2 conflict-free LDS.128.
    __shared__ float2 tile[34 * TS2];
    __shared__ ull grp[8], grn[8];   // packed {r,r}, {-r,-r}, r = tan(theta/2)
    __shared__ ull gq[8];            // packed {-2/(1+r^2)} (layer-2 norm factor folded in)

    const int tid  = threadIdx.x;
    const int img0 = blockIdx.x * 2;

    if (tid < 8) {
        float sv, cv;
        sincosf(w[tid] * 0.5f, &sv, &cv);
        float r = __fdividef(sv, cv);   // global cosine factors cancel in <Z> ratio
        grp[tid] = pack2(r, r);
        grn[tid] = pack2(-r, -r);
        float q  = __fdividef(-2.0f, fmaf(r, r, 1.0f));
        gq[tid]  = pack2(q, q);
    }

    // Zero padding (float4 = 2 interleaved pixels): right cols 32..35 rows 0..33,
    // bottom rows 32..33 cols 0..31.
    {
        const float4 z4 = make_float4(0.f, 0.f, 0.f, 0.f);
        if (tid < 68) {
            int r = tid >> 1, half = tid & 1;
            *reinterpret_cast<float4*>(&tile[r * TS2 + 32 + half * 2]) = z4;
        } else if (tid < 100) {
            int t = tid - 68;                  // 0..31
            int r = 32 + (t >> 4), qi = t & 15;
            *reinterpret_cast<float4*>(&tile[r * TS2 + qi * 2]) = z4;
        }
    }

    // Coalesced load of both 32x32 images, stored interleaved (2 STS.128/thread)
    {
        float4 v0 = x4[img0 * 256 + tid];
        float4 v1 = x4[(img0 + 1) * 256 + tid];
        int r = tid >> 3, c4 = (tid & 7) << 2;
        float4 lo = make_float4(v0.x, v1.x, v0.y, v1.y);   // cols c4, c4+1
        float4 hi = make_float4(v0.z, v1.z, v0.w, v1.w);   // cols c4+2, c4+3
        *reinterpret_cast<float4*>(&tile[r * TS2 + c4])     = lo;
        *reinterpret_cast<float4*>(&tile[r * TS2 + c4 + 2]) = hi;
    }
    __syncthreads();

    // Patch tid = (ph, pw): rows 2ph..2ph+3, cols 2pw..2pw+3 of the padded 34x34.
    const int ph = tid >> 4, pw = tid & 15;
    const ulonglong2* p4 = reinterpret_cast<const ulonglong2*>(tile);
    const int b4 = (ph * 2) * (TS2 / 2) + pw;   // float4 index of patch row start

    // Amplitudes packed {img0,img1}: j = dr*4+dc; wire0 = MSB (mask 8).
    // 8 LDS.128, each yielding two packed amplitudes directly (no MOVs).
    ull a[16];
#pragma unroll
    for (int dr = 0; dr < 4; ++dr) {
        ulonglong2 q0 = p4[b4 + dr * (TS2 / 2)];        // dc 0,1
        ulonglong2 q1 = p4[b4 + dr * (TS2 / 2) + 1];    // dc 2,3
        a[dr * 4 + 0] = q0.x;
        a[dr * 4 + 1] = q0.y;
        a[dr * 4 + 2] = q1.x;
        a[dr * 4 + 3] = q1.y;
    }

    // Layer-1 RY (tangent form): new0 = t0 - r*t1 ; new1 = r*t0 + t1
    auto ry = [&](int m, int gi) {
        ull r2  = grp[gi];
        ull nr2 = grn[gi];
#pragma unroll
        for (int j = 0; j < 16; ++j) {
            if (j & m) continue;
            ull t0 = a[j], t1 = a[j | m];
            a[j]     = ffma2(nr2, t1, t0);
            a[j | m] = ffma2(r2,  t0, t1);
        }
    };
    // CNOT = compile-time register permutation (free)
    auto cnot = [&](int cb, int tb) {
#pragma unroll
        for (int j = 0; j < 16; ++j)
            if ((j & cb) && !(j & tb)) { ull t = a[j]; a[j] = a[j | tb]; a[j | tb] = t; }
    };

    ry(8, 0); ry(4, 1); ry(2, 2); ry(1, 3);
    cnot(8, 4); cnot(4, 2); cnot(2, 1); cnot(1, 8);

    // Z-invariance: <Z_w> is invariant under unitaries on other qubits, so after the
    // CNOT ring only layer-2's RY on wire w matters:
    //   s_w  = sum_{j: bit_w clear} (r_w*b[j] + b[j|m])^2
    //   <Z_w> = 1 - 2*s_w / ((1+r_w^2) * sum b^2)     (tangent-form norm factor)
    ull nA = fmul2(a[0], a[0]);
    ull nB = fmul2(a[1], a[1]);
#pragma unroll
    for (int j = 2; j < 16; j += 2) {
        nA = ffma2(a[j],     a[j],     nA);
        nB = ffma2(a[j + 1], a[j + 1], nB);
    }
    ull nrm2 = fadd2(nA, nB);

    ull s[4];
#pragma unroll
    for (int wq = 0; wq < 4; ++wq) {
        const int m = 8 >> wq;
        ull r2 = grp[4 + wq];
        ull acc;
        bool first = true;
#pragma unroll
        for (int j = 0; j < 16; ++j) {
            if (j & m) continue;
            ull u = ffma2(r2, a[j], a[j | m]);
            if (first) { acc = fmul2(u, u); first = false; }
            else       { acc = ffma2(u, u, acc); }
        }
        s[wq] = acc;
    }

    float n0, n1;
    unpack2(nrm2, n0, n1);
    ull inv  = pack2(__fdividef(1.0f, n0), __fdividef(1.0f, n1));
    ull ones = pack2(1.0f, 1.0f);

    float4 o0, o1;
    {
        ull z0 = ffma2(s[0], fmul2(inv, gq[4]), ones);
        ull z1 = ffma2(s[1], fmul2(inv, gq[5]), ones);
        ull z2 = ffma2(s[2], fmul2(inv, gq[6]), ones);
        ull z3 = ffma2(s[3], fmul2(inv, gq[7]), ones);
        unpack2(z0, o0.x, o1.x);
        unpack2(z1, o0.y, o1.y);
        unpack2(z2, o0.z, o1.z);
        unpack2(z3, o0.w, o1.w);
    }

    // out[img, p*4 + w] with p = tid -> coalesced float4 stores
    out4[img0 * 256 + tid]       = o0;
    out4[(img0 + 1) * 256 + tid] = o1;
}

extern "C" void kernel_launch(void* const* d_in, const int* in_sizes, int n_in,
                              void* d_out, int out_size)
{
    const float* x = (const float*)d_in[0];
    const float* w = (const float*)d_in[1];
    if (n_in >= 2 && in_sizes[0] == 8) {   // defensive input-order resolution
        x = (const float*)d_in[1];
        w = (const float*)d_in[0];
    }
    quan2d_kernel<<<4096, 256>>>((const float4*)x, w, (float4*)d_out);
}

// round 11
// speedup vs baseline: 1.3835x; 1.0617x over previous
#include <cuda_runtime.h>
#include <cuda_bf16.h>

#define TS2 36   // smem row stride in float2 units (34 used + 2 pad; even -> float4 aligned)

using ull = unsigned long long;

// ---- packed f32x2 helpers (sm_100+ PTX; ptxas never auto-fuses these) ----
__device__ __forceinline__ ull pack2(float lo, float hi) {
    ull r;
    asm("mov.b64 %0, {%1, %2};" : "=l"(r)
        : "r"(__float_as_uint(lo)), "r"(__float_as_uint(hi)));
    return r;
}
__device__ __forceinline__ void unpack2(ull v, float& lo, float& hi) {
    unsigned a, b;
    asm("mov.b64 {%0, %1}, %2;" : "=r"(a), "=r"(b) : "l"(v));
    lo = __uint_as_float(a); hi = __uint_as_float(b);
}
__device__ __forceinline__ ull ffma2(ull a, ull b, ull c) {
    ull d; asm("fma.rn.f32x2 %0, %1, %2, %3;" : "=l"(d) : "l"(a), "l"(b), "l"(c));
    return d;
}
__device__ __forceinline__ ull fmul2(ull a, ull b) {
    ull d; asm("mul.rn.f32x2 %0, %1, %2;" : "=l"(d) : "l"(a), "l"(b));
    return d;
}
__device__ __forceinline__ ull fadd2(ull a, ull b) {
    ull d; asm("add.rn.f32x2 %0, %1, %2;" : "=l"(d) : "l"(a), "l"(b));
    return d;
}

__global__ __launch_bounds__(256, 5)
void quan2d_kernel(const float4* __restrict__ x4,
                   const float* __restrict__ w,
                   float4* __restrict__ out4)
{
    // Interleaved zero-padded 34x34 tile: tile[r*TS2 + c] = { img0[r][c], img1[r][c] }.
    // A patch row (4 cols, even start) = 2 aligned float4 = 2 conflict-free LDS.128.
    __shared__ float2 tile[34 * TS2];
    __shared__ ull grp[8], grn[8];   // packed {r,r}, {-r,-r}, r = tan(theta/2)

    const int tid  = threadIdx.x;
    const int img0 = blockIdx.x * 2;

    if (tid < 8) {
        float sv, cv;
        sincosf(w[tid] * 0.5f, &sv, &cv);
        float r = __fdividef(sv, cv);   // global cosine factors cancel in <Z> ratio
        grp[tid] = pack2(r, r);
        grn[tid] = pack2(-r, -r);
    }

    // Zero padding (float4 = 2 interleaved pixels): right cols 32..35 rows 0..33,
    // bottom rows 32..33 cols 0..31.
    {
        const float4 z4 = make_float4(0.f, 0.f, 0.f, 0.f);
        if (tid < 68) {
            int r = tid >> 1, half = tid & 1;
            *reinterpret_cast<float4*>(&tile[r * TS2 + 32 + half * 2]) = z4;
        } else if (tid < 100) {
            int t = tid - 68;                  // 0..31
            int r = 32 + (t >> 4), qi = t & 15;
            *reinterpret_cast<float4*>(&tile[r * TS2 + qi * 2]) = z4;
        }
    }

    // Coalesced load of both 32x32 images, stored interleaved (2 STS.128/thread)
    {
        float4 v0 = x4[img0 * 256 + tid];
        float4 v1 = x4[(img0 + 1) * 256 + tid];
        int r = tid >> 3, c4 = (tid & 7) << 2;
        float4 lo = make_float4(v0.x, v1.x, v0.y, v1.y);   // cols c4, c4+1
        float4 hi = make_float4(v0.z, v1.z, v0.w, v1.w);   // cols c4+2, c4+3
        *reinterpret_cast<float4*>(&tile[r * TS2 + c4])     = lo;
        *reinterpret_cast<float4*>(&tile[r * TS2 + c4 + 2]) = hi;
    }
    __syncthreads();

    // Patch tid = (ph, pw): rows 2ph..2ph+3, cols 2pw..2pw+3 of the padded 34x34.
    const int ph = tid >> 4, pw = tid & 15;
    const ulonglong2* p4 = reinterpret_cast<const ulonglong2*>(tile);
    const int b4 = (ph * 2) * (TS2 / 2) + pw;   // float4 index of patch row start

    // Amplitudes packed {img0,img1}: j = dr*4+dc; wire0 = MSB (mask 8).
    // 8 LDS.128, each yielding two packed amplitudes directly (no MOVs), batched -> MLP=8.
    ull a[16];
#pragma unroll
    for (int dr = 0; dr < 4; ++dr) {
        ulonglong2 q0 = p4[b4 + dr * (TS2 / 2)];        // dc 0,1
        ulonglong2 q1 = p4[b4 + dr * (TS2 / 2) + 1];    // dc 2,3
        a[dr * 4 + 0] = q0.x;
        a[dr * 4 + 1] = q0.y;
        a[dr * 4 + 2] = q1.x;
        a[dr * 4 + 3] = q1.y;
    }

    // RY (tangent form, cosine deferred): new0 = t0 - r*t1 ; new1 = r*t0 + t1
    // In-place: lowest register liveness (proven no-spill tail).
    auto ry = [&](int m, int gi) {
        ull r2  = grp[gi];
        ull nr2 = grn[gi];
#pragma unroll
        for (int j = 0; j < 16; ++j) {
            if (j & m) continue;
            ull t0 = a[j], t1 = a[j | m];
            a[j]     = ffma2(nr2, t1, t0);
            a[j | m] = ffma2(r2,  t0, t1);
        }
    };
    // CNOT = compile-time register permutation (free)
    auto cnot = [&](int cb, int tb) {
#pragma unroll
        for (int j = 0; j < 16; ++j)
            if ((j & cb) && !(j & tb)) { ull t = a[j]; a[j] = a[j | tb]; a[j | tb] = t; }
    };

    ry(8, 0); ry(4, 1); ry(2, 2); ry(1, 3);
    cnot(8, 4); cnot(4, 2); cnot(2, 1); cnot(1, 8);
    ry(8, 4); ry(4, 5); ry(2, 6); ry(1, 7);

    // Group sums of squares (consumes a[] as it goes -> low liveness):
    //   G[g] = sum a[j]^2, j with (bit3,bit2) = g   (j = g*4 + k)
    //   H[g] = sum a[j]^2, j with (bit1,bit0) = g   (j = k*4 + g)
    ull G[4], H[4];
#pragma unroll
    for (int g = 0; g < 4; ++g) {
        ull acc = fmul2(a[g * 4], a[g * 4]);
#pragma unroll
        for (int k = 1; k < 4; ++k) acc = ffma2(a[g * 4 + k], a[g * 4 + k], acc);
        G[g] = acc;
        ull acc2 = fmul2(a[g], a[g]);
#pragma unroll
        for (int k = 1; k < 4; ++k) acc2 = ffma2(a[k * 4 + g], a[k * 4 + g], acc2);
        H[g] = acc2;
    }
    ull nrm2 = fadd2(fadd2(G[0], G[1]), fadd2(G[2], G[3]));
    ull s0p = fadd2(G[2], G[3]);   // wire0 (bit3 set)
    ull s1p = fadd2(G[1], G[3]);   // wire1 (bit2 set)
    ull s2p = fadd2(H[2], H[3]);   // wire2 (bit1 set)
    ull s3p = fadd2(H[1], H[3]);   // wire3 (bit0 set)

    // <Z_w> = 1 - 2*s_w/nrm
    float n0, n1;
    unpack2(nrm2, n0, n1);
    ull m2inv = pack2(__fdividef(-2.0f, n0), __fdividef(-2.0f, n1));
    ull ones  = pack2(1.0f, 1.0f);

    ull z0 = ffma2(s0p, m2inv, ones);
    ull z1 = ffma2(s1p, m2inv, ones);
    ull z2 = ffma2(s2p, m2inv, ones);
    ull z3 = ffma2(s3p, m2inv, ones);

    float4 o0, o1;
    unpack2(z0, o0.x, o1.x);
    unpack2(z1, o0.y, o1.y);
    unpack2(z2, o0.z, o1.z);
    unpack2(z3, o0.w, o1.w);

    // out[img, p*4 + w] with p = tid -> coalesced float4 stores
    out4[img0 * 256 + tid]       = o0;
    out4[(img0 + 1) * 256 + tid] = o1;
}

extern "C" void kernel_launch(void* const* d_in, const int* in_sizes, int n_in,
                              void* d_out, int out_size)
{
    const float* x = (const float*)d_in[0];
    const float* w = (const float*)d_in[1];
    if (n_in >= 2 && in_sizes[0] == 8) {   // defensive input-order resolution
        x = (const float*)d_in[1];
        w = (const float*)d_in[0];
    }
    quan2d_kernel<<<4096, 256>>>((const float4*)x, w, (float4*)d_out);
}